// round 15
// baseline (speedup 1.0000x reference)
#include <cuda_runtime.h>
#include <math.h>

// sym_logm of B SPD 64x64 fp32 matrices.
// R14 = R13 champion jacobi (untouched math) + epilogue rework + ncu aiming.
//  - Launch order (dummy, jacobi, epilogue, dummy): ncu's -s 5 -c 1 now lands
//    on JACOBI (5 mod 4 == 1) instead of always profiling the epilogue.
//  - g_Q scratch dropped: jacobi stores only P + per-column weights g_W;
//    epilogue computes out[i][j] = sum_k w_k P[k][i] P[k][j] with 4x4
//    register tiling (2 LDS.128 + 16 FMA per k vs 5 LDS per 16 FMA before)
//    -> attacks the measured L1=93.6% bound; kills 268MB of Q traffic.
// Kernel 1: one-warp-per-block Hestenes Jacobi with SMEM parking, (32,10).

#define MAXB 8192
#define NMAT 64
#define FULLM 0xffffffffu
#define TH2 4e-9f
typedef unsigned long long u64;

__device__ float g_P[(size_t)MAXB * NMAT * NMAT];
__device__ float g_W[(size_t)MAXB * NMAT];

__device__ __forceinline__ u64 pk(float lo, float hi) {
    u64 r; asm("mov.b64 %0,{%1,%2};" : "=l"(r) : "f"(lo), "f"(hi)); return r;
}
__device__ __forceinline__ void upk(u64 v, float& lo, float& hi) {
    asm("mov.b64 {%0,%1},%2;" : "=f"(lo), "=f"(hi) : "l"(v));
}
__device__ __forceinline__ u64 fma2_(u64 a, u64 b, u64 c) {
    u64 d; asm("fma.rn.f32x2 %0,%1,%2,%3;" : "=l"(d) : "l"(a), "l"(b), "l"(c)); return d;
}
__device__ __forceinline__ u64 mul2_(u64 a, u64 b) {
    u64 d; asm("mul.rn.f32x2 %0,%1,%2;" : "=l"(d) : "l"(a), "l"(b)); return d;
}

__device__ __forceinline__ void angle_(float np, float nq, float apq,
                                       float& c, float& s, float& t)
{
    float th = __fdividef(0.5f * (nq - np), apq);
    t = __fdividef(copysignf(1.0f, th), fabsf(th) + sqrtf(fmaf(th, th, 1.0f)));
    c = rsqrtf(fmaf(t, t, 1.0f));
    s = t * c;
}

__device__ __forceinline__ int sideA(u64* C, float& n, int mm, bool amP)
{
    u64 R[32];
    #pragma unroll
    for (int j = 0; j < 32; ++j) R[j] = __shfl_xor_sync(FULLM, C[j], mm);

    u64 a0 = 0, a1 = 0, a2 = 0, a3 = 0;
    #pragma unroll
    for (int j = 0; j < 32; j += 4) {
        a0 = fma2_(C[j],   R[j],   a0);
        a1 = fma2_(C[j+1], R[j+1], a1);
        a2 = fma2_(C[j+2], R[j+2], a2);
        a3 = fma2_(C[j+3], R[j+3], a3);
    }
    float l0, h0, l1, h1, l2, h2, l3, h3;
    upk(a0, l0, h0); upk(a1, l1, h1); upk(a2, l2, h2); upk(a3, l3, h3);
    float apq = ((l0 + h0) + (l1 + h1)) + ((l2 + h2) + (l3 + h3));
    float pn  = __shfl_xor_sync(FULLM, n, mm);

    bool rot = (apq * apq > TH2 * n * pn);
    int active = (int)__any_sync(FULLM, rot);
    if (active) {
        float c = 1.0f, se = 0.0f;
        if (rot) {
            float np = amP ? n  : pn;
            float nq = amP ? pn : n;
            float cc, ss, t;
            angle_(np, nq, apq, cc, ss, t);
            c  = cc;
            se = amP ? -ss : ss;
            n  = fmaf(amP ? -t : t, apq, n);
        }
        u64 c2 = pk(c, c), se2 = pk(se, se);
        #pragma unroll
        for (int j = 0; j < 32; ++j)
            C[j] = fma2_(c2, C[j], mul2_(se2, R[j]));
    }
    return active;
}

__global__ void dummy_k(int x) { if (x == 12345) g_W[0] = 0.0f; }  // no-op aimer

__global__ __launch_bounds__(32, 10) void jacobi_park(const float* __restrict__ Xg, int B)
{
    __shared__ u64   park[32 * 33];
    __shared__ float parkN[32];

    const int b    = blockIdx.x;
    const int lane = threadIdx.x;

    u64 X[32];
    u64 Y[32];

    float nP = 0.0f;
    {
        const float4* x4 = (const float4*)(Xg + (size_t)b * 4096);
        #pragma unroll
        for (int r = 0; r < 16; ++r) {
            float4 v = x4[lane * 16 + r];
            X[2*r] = pk(v.x, v.y); X[2*r+1] = pk(v.z, v.w);
            float4 w = x4[(lane + 32) * 16 + r];
            park[(2*r)   * 33 + lane] = pk(w.x, w.y);
            park[(2*r+1) * 33 + lane] = pk(w.z, w.w);
            nP = fmaf(w.x, w.x, fmaf(w.y, w.y, fmaf(w.z, w.z, fmaf(w.w, w.w, nP))));
        }
        parkN[lane] = nP;
    }
    float nX;
    {
        u64 a = 0;
        #pragma unroll
        for (int j = 0; j < 32; ++j) a = fma2_(X[j], X[j], a);
        float lo, hi; upk(a, lo, hi); nX = lo + hi;
    }
    float nY = 0.0f;

    for (int sweep = 0; sweep < 28; ++sweep) {
        int any = 0;

        // ---- Phase A on C0 (C1 parked) ----
        #pragma unroll 1
        for (int mm = 1; mm < 32; ++mm)
            any |= sideA(X, nX, mm, lane < (lane ^ mm));

        // ---- swap active <-> parked ----
        #pragma unroll
        for (int j = 0; j < 32; ++j) {
            u64 t = park[j * 33 + lane];
            park[j * 33 + lane] = X[j];
            X[j] = t;
        }
        { float t = parkN[lane]; parkN[lane] = nX; nX = t; }

        // ---- Phase A on C1 (C0 parked) ----
        #pragma unroll 1
        for (int mm = 1; mm < 32; ++mm)
            any |= sideA(X, nX, mm, lane < (lane ^ mm));

        // ---- unpark C0 into Y ----
        #pragma unroll
        for (int j = 0; j < 32; ++j) Y[j] = park[j * 33 + lane];
        nY = parkN[lane];

        // ---- Cross phase: lane-local pairs (Y p-side, X q-side) ----
        #pragma unroll 1
        for (int k = 0; k < 32; ++k) {
            u64 a0 = 0, a1 = 0, a2 = 0, a3 = 0;
            #pragma unroll
            for (int j = 0; j < 32; j += 4) {
                a0 = fma2_(Y[j],   X[j],   a0);
                a1 = fma2_(Y[j+1], X[j+1], a1);
                a2 = fma2_(Y[j+2], X[j+2], a2);
                a3 = fma2_(Y[j+3], X[j+3], a3);
            }
            float l0, h0, l1, h1, l2, h2, l3, h3;
            upk(a0, l0, h0); upk(a1, l1, h1); upk(a2, l2, h2); upk(a3, l3, h3);
            float apq = ((l0 + h0) + (l1 + h1)) + ((l2 + h2) + (l3 + h3));

            bool rot = (apq * apq > TH2 * nY * nX);
            if (__any_sync(FULLM, rot)) {
                float c = 1.0f, s = 0.0f;
                if (rot) {
                    float cc, ss, t;
                    angle_(nY, nX, apq, cc, ss, t);
                    c = cc; s = ss;
                    nY = fmaf(-t, apq, nY);
                    nX = fmaf( t, apq, nX);
                    any = 1;
                }
                u64 c2 = pk(c, c), s2 = pk(s, s), ns2 = pk(-s, -s);
                #pragma unroll
                for (int j = 0; j < 32; ++j) {
                    u64 y = Y[j];
                    Y[j] = fma2_(c2, y, mul2_(ns2, X[j]));
                    X[j] = fma2_(s2, y, mul2_(c2,  X[j]));
                }
            }
            #pragma unroll
            for (int j = 0; j < 32; ++j) X[j] = __shfl_sync(FULLM, X[j], lane + 1);
            nX = __shfl_sync(FULLM, nX, lane + 1);
        }

        if (!__any_sync(FULLM, any) || sweep == 27) break;

        {
            u64 a = 0, bsum = 0;
            #pragma unroll
            for (int j = 0; j < 32; ++j) { a = fma2_(Y[j], Y[j], a); bsum = fma2_(X[j], X[j], bsum); }
            float lo, hi; upk(a, lo, hi); nY = lo + hi; upk(bsum, lo, hi); nX = lo + hi;
        }
        #pragma unroll
        for (int j = 0; j < 32; ++j) {
            park[j * 33 + lane] = X[j];
            X[j] = Y[j];
        }
        parkN[lane] = nX;
        nX = nY;
    }

    // exact norms -> weights w = 0.5*log(n)/n ; store P and weights only
    float e0, e1;
    {
        u64 a0 = 0, a1 = 0;
        #pragma unroll
        for (int j = 0; j < 32; ++j) { a0 = fma2_(Y[j], Y[j], a0); a1 = fma2_(X[j], X[j], a1); }
        float lo, hi; upk(a0, lo, hi); e0 = lo + hi; upk(a1, lo, hi); e1 = lo + hi;
    }
    float w0 = 0.5f * logf(fmaxf(e0, 1e-30f)) / e0;
    float w1 = 0.5f * logf(fmaxf(e1, 1e-30f)) / e1;

    u64* Pp = (u64*)(g_P + (size_t)b * 4096);
    #pragma unroll
    for (int j = 0; j < 32; ++j) {
        Pp[lane * 32 + j]        = Y[j];
        Pp[(lane + 32) * 32 + j] = X[j];
    }
    g_W[b * NMAT + lane]      = w0;
    g_W[b * NMAT + lane + 32] = w1;
}

// out[b][i][j] = sum_k w_k * P[b][k][i] * P[b][k][j]   (4x4 register tiles)
__global__ __launch_bounds__(256) void gram_epilogue(float* __restrict__ out, int B)
{
    __shared__ float Ps[NMAT * NMAT];   // [k][row], row contiguous
    __shared__ float ws[NMAT];
    const int b = blockIdx.x;
    const int tid = threadIdx.x;
    const float* Pb = g_P + (size_t)b * (NMAT * NMAT);

    {
        const float4* src = (const float4*)Pb;
        float4* dst = (float4*)Ps;
        #pragma unroll
        for (int i = tid; i < NMAT * NMAT / 4; i += 256) dst[i] = src[i];
        if (tid < NMAT) ws[tid] = g_W[b * NMAT + tid];
    }
    __syncthreads();

    const int tx = tid & 15;        // col group: cols 4*tx..4*tx+3
    const int ty = tid >> 4;        // row group: rows 4*ty..4*ty+3
    float acc[4][4];
    #pragma unroll
    for (int r = 0; r < 4; ++r)
        #pragma unroll
        for (int c = 0; c < 4; ++c) acc[r][c] = 0.0f;

    #pragma unroll 4
    for (int k = 0; k < NMAT; ++k) {
        float wk = ws[k];
        float4 a = *(const float4*)&Ps[k * NMAT + 4 * ty];   // rows
        float4 q = *(const float4*)&Ps[k * NMAT + 4 * tx];   // cols
        float q0 = q.x * wk, q1 = q.y * wk, q2 = q.z * wk, q3 = q.w * wk;
        acc[0][0] = fmaf(a.x, q0, acc[0][0]); acc[0][1] = fmaf(a.x, q1, acc[0][1]);
        acc[0][2] = fmaf(a.x, q2, acc[0][2]); acc[0][3] = fmaf(a.x, q3, acc[0][3]);
        acc[1][0] = fmaf(a.y, q0, acc[1][0]); acc[1][1] = fmaf(a.y, q1, acc[1][1]);
        acc[1][2] = fmaf(a.y, q2, acc[1][2]); acc[1][3] = fmaf(a.y, q3, acc[1][3]);
        acc[2][0] = fmaf(a.z, q0, acc[2][0]); acc[2][1] = fmaf(a.z, q1, acc[2][1]);
        acc[2][2] = fmaf(a.z, q2, acc[2][2]); acc[2][3] = fmaf(a.z, q3, acc[2][3]);
        acc[3][0] = fmaf(a.w, q0, acc[3][0]); acc[3][1] = fmaf(a.w, q1, acc[3][1]);
        acc[3][2] = fmaf(a.w, q2, acc[3][2]); acc[3][3] = fmaf(a.w, q3, acc[3][3]);
    }

    float* Ob = out + (size_t)b * (NMAT * NMAT);
    #pragma unroll
    for (int r = 0; r < 4; ++r) {
        float4 v = make_float4(acc[r][0], acc[r][1], acc[r][2], acc[r][3]);
        *(float4*)&Ob[(4 * ty + r) * NMAT + 4 * tx] = v;
    }
}

extern "C" void kernel_launch(void* const* d_in, const int* in_sizes, int n_in,
                              void* d_out, int out_size) {
    const float* X = (const float*)d_in[0];
    float* out = (float*)d_out;
    int B = in_sizes[0] / (NMAT * NMAT);
    if (B > MAXB) B = MAXB;
    dummy_k<<<1, 32>>>(0);                 // launch-index aimer: puts jacobi at
    jacobi_park<<<B, 32>>>(X, B);          // ncu's -s 5 (5 mod 4 == 1)
    gram_epilogue<<<B, 256>>>(out, B);
    dummy_k<<<1, 32>>>(0);
}

// round 17
// speedup vs baseline: 1.0041x; 1.0041x over previous
#include <cuda_runtime.h>
#include <math.h>

// sym_logm of B SPD 64x64 fp32 matrices.
// R15 = bisect of the R14 regression: R14 minus the dummy aimer launches.
//   Launcher is back to exactly (jacobi, epilogue). Jacobi = R13 champion,
//   bit-identical math (rel_err must reproduce 2.039e-4 exactly).
//   Epilogue keeps the R14 rework: no g_Q scratch (weights in g_W, folded
//   into the accumulation), 4x4 register tiling, float4 global+shared I/O.
// Kernel 1: one-warp-per-block Hestenes Jacobi with SMEM parking, (32,10).
// Kernel 2: out[b][i][j] = sum_k w_k P[b][k][i] P[b][k][j].

#define MAXB 8192
#define NMAT 64
#define FULLM 0xffffffffu
#define TH2 4e-9f
typedef unsigned long long u64;

__device__ float g_P[(size_t)MAXB * NMAT * NMAT];
__device__ float g_W[(size_t)MAXB * NMAT];

__device__ __forceinline__ u64 pk(float lo, float hi) {
    u64 r; asm("mov.b64 %0,{%1,%2};" : "=l"(r) : "f"(lo), "f"(hi)); return r;
}
__device__ __forceinline__ void upk(u64 v, float& lo, float& hi) {
    asm("mov.b64 {%0,%1},%2;" : "=f"(lo), "=f"(hi) : "l"(v));
}
__device__ __forceinline__ u64 fma2_(u64 a, u64 b, u64 c) {
    u64 d; asm("fma.rn.f32x2 %0,%1,%2,%3;" : "=l"(d) : "l"(a), "l"(b), "l"(c)); return d;
}
__device__ __forceinline__ u64 mul2_(u64 a, u64 b) {
    u64 d; asm("mul.rn.f32x2 %0,%1,%2;" : "=l"(d) : "l"(a), "l"(b)); return d;
}

__device__ __forceinline__ void angle_(float np, float nq, float apq,
                                       float& c, float& s, float& t)
{
    float th = __fdividef(0.5f * (nq - np), apq);
    t = __fdividef(copysignf(1.0f, th), fabsf(th) + sqrtf(fmaf(th, th, 1.0f)));
    c = rsqrtf(fmaf(t, t, 1.0f));
    s = t * c;
}

__device__ __forceinline__ int sideA(u64* C, float& n, int mm, bool amP)
{
    u64 R[32];
    #pragma unroll
    for (int j = 0; j < 32; ++j) R[j] = __shfl_xor_sync(FULLM, C[j], mm);

    u64 a0 = 0, a1 = 0, a2 = 0, a3 = 0;
    #pragma unroll
    for (int j = 0; j < 32; j += 4) {
        a0 = fma2_(C[j],   R[j],   a0);
        a1 = fma2_(C[j+1], R[j+1], a1);
        a2 = fma2_(C[j+2], R[j+2], a2);
        a3 = fma2_(C[j+3], R[j+3], a3);
    }
    float l0, h0, l1, h1, l2, h2, l3, h3;
    upk(a0, l0, h0); upk(a1, l1, h1); upk(a2, l2, h2); upk(a3, l3, h3);
    float apq = ((l0 + h0) + (l1 + h1)) + ((l2 + h2) + (l3 + h3));
    float pn  = __shfl_xor_sync(FULLM, n, mm);

    bool rot = (apq * apq > TH2 * n * pn);
    int active = (int)__any_sync(FULLM, rot);
    if (active) {
        float c = 1.0f, se = 0.0f;
        if (rot) {
            float np = amP ? n  : pn;
            float nq = amP ? pn : n;
            float cc, ss, t;
            angle_(np, nq, apq, cc, ss, t);
            c  = cc;
            se = amP ? -ss : ss;
            n  = fmaf(amP ? -t : t, apq, n);
        }
        u64 c2 = pk(c, c), se2 = pk(se, se);
        #pragma unroll
        for (int j = 0; j < 32; ++j)
            C[j] = fma2_(c2, C[j], mul2_(se2, R[j]));
    }
    return active;
}

__global__ __launch_bounds__(32, 10) void jacobi_park(const float* __restrict__ Xg, int B)
{
    __shared__ u64   park[32 * 33];
    __shared__ float parkN[32];

    const int b    = blockIdx.x;
    const int lane = threadIdx.x;

    u64 X[32];
    u64 Y[32];

    float nP = 0.0f;
    {
        const float4* x4 = (const float4*)(Xg + (size_t)b * 4096);
        #pragma unroll
        for (int r = 0; r < 16; ++r) {
            float4 v = x4[lane * 16 + r];
            X[2*r] = pk(v.x, v.y); X[2*r+1] = pk(v.z, v.w);
            float4 w = x4[(lane + 32) * 16 + r];
            park[(2*r)   * 33 + lane] = pk(w.x, w.y);
            park[(2*r+1) * 33 + lane] = pk(w.z, w.w);
            nP = fmaf(w.x, w.x, fmaf(w.y, w.y, fmaf(w.z, w.z, fmaf(w.w, w.w, nP))));
        }
        parkN[lane] = nP;
    }
    float nX;
    {
        u64 a = 0;
        #pragma unroll
        for (int j = 0; j < 32; ++j) a = fma2_(X[j], X[j], a);
        float lo, hi; upk(a, lo, hi); nX = lo + hi;
    }
    float nY = 0.0f;

    for (int sweep = 0; sweep < 28; ++sweep) {
        int any = 0;

        // ---- Phase A on C0 (C1 parked) ----
        #pragma unroll 1
        for (int mm = 1; mm < 32; ++mm)
            any |= sideA(X, nX, mm, lane < (lane ^ mm));

        // ---- swap active <-> parked ----
        #pragma unroll
        for (int j = 0; j < 32; ++j) {
            u64 t = park[j * 33 + lane];
            park[j * 33 + lane] = X[j];
            X[j] = t;
        }
        { float t = parkN[lane]; parkN[lane] = nX; nX = t; }

        // ---- Phase A on C1 (C0 parked) ----
        #pragma unroll 1
        for (int mm = 1; mm < 32; ++mm)
            any |= sideA(X, nX, mm, lane < (lane ^ mm));

        // ---- unpark C0 into Y ----
        #pragma unroll
        for (int j = 0; j < 32; ++j) Y[j] = park[j * 33 + lane];
        nY = parkN[lane];

        // ---- Cross phase: lane-local pairs (Y p-side, X q-side) ----
        #pragma unroll 1
        for (int k = 0; k < 32; ++k) {
            u64 a0 = 0, a1 = 0, a2 = 0, a3 = 0;
            #pragma unroll
            for (int j = 0; j < 32; j += 4) {
                a0 = fma2_(Y[j],   X[j],   a0);
                a1 = fma2_(Y[j+1], X[j+1], a1);
                a2 = fma2_(Y[j+2], X[j+2], a2);
                a3 = fma2_(Y[j+3], X[j+3], a3);
            }
            float l0, h0, l1, h1, l2, h2, l3, h3;
            upk(a0, l0, h0); upk(a1, l1, h1); upk(a2, l2, h2); upk(a3, l3, h3);
            float apq = ((l0 + h0) + (l1 + h1)) + ((l2 + h2) + (l3 + h3));

            bool rot = (apq * apq > TH2 * nY * nX);
            if (__any_sync(FULLM, rot)) {
                float c = 1.0f, s = 0.0f;
                if (rot) {
                    float cc, ss, t;
                    angle_(nY, nX, apq, cc, ss, t);
                    c = cc; s = ss;
                    nY = fmaf(-t, apq, nY);
                    nX = fmaf( t, apq, nX);
                    any = 1;
                }
                u64 c2 = pk(c, c), s2 = pk(s, s), ns2 = pk(-s, -s);
                #pragma unroll
                for (int j = 0; j < 32; ++j) {
                    u64 y = Y[j];
                    Y[j] = fma2_(c2, y, mul2_(ns2, X[j]));
                    X[j] = fma2_(s2, y, mul2_(c2,  X[j]));
                }
            }
            #pragma unroll
            for (int j = 0; j < 32; ++j) X[j] = __shfl_sync(FULLM, X[j], lane + 1);
            nX = __shfl_sync(FULLM, nX, lane + 1);
        }

        if (!__any_sync(FULLM, any) || sweep == 27) break;

        {
            u64 a = 0, bsum = 0;
            #pragma unroll
            for (int j = 0; j < 32; ++j) { a = fma2_(Y[j], Y[j], a); bsum = fma2_(X[j], X[j], bsum); }
            float lo, hi; upk(a, lo, hi); nY = lo + hi; upk(bsum, lo, hi); nX = lo + hi;
        }
        #pragma unroll
        for (int j = 0; j < 32; ++j) {
            park[j * 33 + lane] = X[j];
            X[j] = Y[j];
        }
        parkN[lane] = nX;
        nX = nY;
    }

    // exact norms -> weights w = 0.5*log(n)/n ; store P and weights only
    float e0, e1;
    {
        u64 a0 = 0, a1 = 0;
        #pragma unroll
        for (int j = 0; j < 32; ++j) { a0 = fma2_(Y[j], Y[j], a0); a1 = fma2_(X[j], X[j], a1); }
        float lo, hi; upk(a0, lo, hi); e0 = lo + hi; upk(a1, lo, hi); e1 = lo + hi;
    }
    float w0 = 0.5f * logf(fmaxf(e0, 1e-30f)) / e0;
    float w1 = 0.5f * logf(fmaxf(e1, 1e-30f)) / e1;

    u64* Pp = (u64*)(g_P + (size_t)b * 4096);
    #pragma unroll
    for (int j = 0; j < 32; ++j) {
        Pp[lane * 32 + j]        = Y[j];
        Pp[(lane + 32) * 32 + j] = X[j];
    }
    g_W[b * NMAT + lane]      = w0;
    g_W[b * NMAT + lane + 32] = w1;
}

// out[b][i][j] = sum_k w_k * P[b][k][i] * P[b][k][j]   (4x4 register tiles)
__global__ __launch_bounds__(256) void gram_epilogue(float* __restrict__ out, int B)
{
    __shared__ float Ps[NMAT * NMAT];   // [k][row], row contiguous
    __shared__ float ws[NMAT];
    const int b = blockIdx.x;
    const int tid = threadIdx.x;
    const float* Pb = g_P + (size_t)b * (NMAT * NMAT);

    {
        const float4* src = (const float4*)Pb;
        float4* dst = (float4*)Ps;
        #pragma unroll
        for (int i = tid; i < NMAT * NMAT / 4; i += 256) dst[i] = src[i];
        if (tid < NMAT) ws[tid] = g_W[b * NMAT + tid];
    }
    __syncthreads();

    const int tx = tid & 15;        // col group: cols 4*tx..4*tx+3
    const int ty = tid >> 4;        // row group: rows 4*ty..4*ty+3
    float acc[4][4];
    #pragma unroll
    for (int r = 0; r < 4; ++r)
        #pragma unroll
        for (int c = 0; c < 4; ++c) acc[r][c] = 0.0f;

    #pragma unroll 4
    for (int k = 0; k < NMAT; ++k) {
        float wk = ws[k];
        float4 a = *(const float4*)&Ps[k * NMAT + 4 * ty];   // rows
        float4 q = *(const float4*)&Ps[k * NMAT + 4 * tx];   // cols
        float q0 = q.x * wk, q1 = q.y * wk, q2 = q.z * wk, q3 = q.w * wk;
        acc[0][0] = fmaf(a.x, q0, acc[0][0]); acc[0][1] = fmaf(a.x, q1, acc[0][1]);
        acc[0][2] = fmaf(a.x, q2, acc[0][2]); acc[0][3] = fmaf(a.x, q3, acc[0][3]);
        acc[1][0] = fmaf(a.y, q0, acc[1][0]); acc[1][1] = fmaf(a.y, q1, acc[1][1]);
        acc[1][2] = fmaf(a.y, q2, acc[1][2]); acc[1][3] = fmaf(a.y, q3, acc[1][3]);
        acc[2][0] = fmaf(a.z, q0, acc[2][0]); acc[2][1] = fmaf(a.z, q1, acc[2][1]);
        acc[2][2] = fmaf(a.z, q2, acc[2][2]); acc[2][3] = fmaf(a.z, q3, acc[2][3]);
        acc[3][0] = fmaf(a.w, q0, acc[3][0]); acc[3][1] = fmaf(a.w, q1, acc[3][1]);
        acc[3][2] = fmaf(a.w, q2, acc[3][2]); acc[3][3] = fmaf(a.w, q3, acc[3][3]);
    }

    float* Ob = out + (size_t)b * (NMAT * NMAT);
    #pragma unroll
    for (int r = 0; r < 4; ++r) {
        float4 v = make_float4(acc[r][0], acc[r][1], acc[r][2], acc[r][3]);
        *(float4*)&Ob[(4 * ty + r) * NMAT + 4 * tx] = v;
    }
}

extern "C" void kernel_launch(void* const* d_in, const int* in_sizes, int n_in,
                              void* d_out, int out_size) {
    const float* X = (const float*)d_in[0];
    float* out = (float*)d_out;
    int B = in_sizes[0] / (NMAT * NMAT);
    if (B > MAXB) B = MAXB;
    jacobi_park<<<B, 32>>>(X, B);
    gram_epilogue<<<B, 256>>>(out, B);
}